// round 4
// baseline (speedup 1.0000x reference)
#include <cuda_runtime.h>

#define N_MAX 100000
#define E_MAX 1700000

// ---------------- static device scratch (referenced directly in kernels) -----
__device__ __align__(16) float g_t[(size_t)N_MAX * 64];  // GEMM out / prop in
__device__ __align__(16) float g_h[(size_t)N_MAX * 64];  // prop out / GEMM in
__device__ int   g_src[E_MAX];               // CSR: source node per edge (by dst)
__device__ float g_w[E_MAX];                 // CSR: norm weight per edge
__device__ int   g_deg[N_MAX];               // in-degree (incl self loop)
__device__ int   g_cur[N_MAX];               // scatter cursors
__device__ int   g_off[N_MAX + 1];           // CSR row offsets (by dst)
__device__ float g_dinv[N_MAX];              // deg^-1/2
__device__ int   g_bsums[256];               // scan block sums

// ---------------- graph preprocessing ----------------
__global__ void k_init(int n) {
    int i = blockIdx.x * blockDim.x + threadIdx.x;
    if (i < n) { g_deg[i] = 1; g_cur[i] = 0; }   // deg starts at 1: self loop
}

// edge_index is int32 (JAX x64 disabled downcasts jnp.int64 -> int32)
__global__ void k_count(const int* __restrict__ ei, int E) {
    int e = blockIdx.x * blockDim.x + threadIdx.x;
    if (e < E) atomicAdd(&g_deg[ei[E + e]], 1);
}

// scan of (deg-1) over 1024-elem tiles, shuffle-based, fused dinv computation
__global__ __launch_bounds__(256) void k_scan1(int n) {
    __shared__ int wsum[8];
    int tid = threadIdx.x;
    int base = blockIdx.x * 1024 + tid * 4;
    int v[4];
#pragma unroll
    for (int j = 0; j < 4; j++) {
        int i = base + j;
        int d = (i < n) ? g_deg[i] : 1;
        v[j] = d - 1;
        if (i < n) g_dinv[i] = rsqrtf((float)d);
    }
    int s = v[0] + v[1] + v[2] + v[3];
    int lane = tid & 31, w = tid >> 5;
    int ps = s;
#pragma unroll
    for (int o = 1; o < 32; o <<= 1) {
        int t = __shfl_up_sync(0xffffffffu, ps, o);
        if (lane >= o) ps += t;
    }
    if (lane == 31) wsum[w] = ps;
    __syncthreads();
    if (w == 0) {
        int t = (lane < 8) ? wsum[lane] : 0;
#pragma unroll
        for (int o = 1; o < 8; o <<= 1) {
            int u = __shfl_up_sync(0xffffffffu, t, o);
            if (lane >= o) t += u;
        }
        if (lane < 8) wsum[lane] = t;
    }
    __syncthreads();
    int run = ps - s + (w ? wsum[w - 1] : 0);   // block-local exclusive
#pragma unroll
    for (int j = 0; j < 4; j++) {
        int i = base + j;
        if (i < n) g_off[i] = run;
        run += v[j];
    }
    if (tid == 0) g_bsums[blockIdx.x] = wsum[7];
}

__global__ void k_scan2(int nb) {
    __shared__ int sh[256];
    int tid = threadIdx.x;
    int v = (tid < nb) ? g_bsums[tid] : 0;
    sh[tid] = v;
    __syncthreads();
    for (int o = 1; o < 256; o <<= 1) {
        int t = (tid >= o) ? sh[tid - o] : 0;
        __syncthreads();
        sh[tid] += t;
        __syncthreads();
    }
    if (tid < nb) g_bsums[tid] = sh[tid] - v;    // exclusive
}

__global__ void k_scanadd(int n, int E) {
    int i = blockIdx.x * blockDim.x + threadIdx.x;
    if (i < n) g_off[i] += g_bsums[i >> 10];
    if (i == 0) g_off[n] = E;
}

__global__ void k_scatter(const int* __restrict__ ei, int E) {
    int e = blockIdx.x * blockDim.x + threadIdx.x;
    if (e >= E) return;
    int s = ei[e];
    int d = ei[E + e];
    int pos = g_off[d] + atomicAdd(&g_cur[d], 1);
    g_src[pos] = s;
    g_w[pos] = g_dinv[s] * g_dinv[d];
}

// ---------------- packed f32x2 helpers ----------------
__device__ __forceinline__ unsigned long long dup2(float x) {
    unsigned long long r;
    asm("mov.b64 %0, {%1, %1};" : "=l"(r) : "f"(x));
    return r;
}
__device__ __forceinline__ void ffma2(unsigned long long& d,
                                      unsigned long long a, unsigned long long b) {
    asm("fma.rn.f32x2 %0, %1, %2, %0;" : "+l"(d) : "l"(a), "l"(b));
}
__device__ __forceinline__ float2 unpk(unsigned long long v) {
    float2 r;
    asm("mov.b64 {%0, %1}, %2;" : "=f"(r.x), "=f"(r.y) : "l"(v));
    return r;
}

// ---------------- GEMM: g_t[n,64] = A[n,K] @ W[K,64] ----------------
// A == nullptr -> read g_h. Tile 128x64, 256 threads, per-thread 4 rows x 8 cols.
// X row-major padded-33 in shared (conflict-free STS + broadcast LDS),
// W loads broadcast across 4-lane groups. Inner loop is FMA-pipe-bound.
template <int K>
__global__ __launch_bounds__(256) void k_gemm(const float* __restrict__ Ain,
                                              const float* __restrict__ W, int n) {
    const float* A = Ain ? Ain : g_h;
    constexpr int KC = 32;
    constexpr int XP = 33;                           // pad: bank = (row+k)%32
    __shared__ float Xs[128 * XP];                   // [row][k_local]
    __shared__ __align__(16) float Wsh[KC * 64];

    int tid = threadIdx.x;
    int row0 = blockIdx.x * 128;
    int tx = tid & 7;            // 8 col groups of 8
    int ty = tid >> 3;           // 32 row groups of 4
    int r0 = ty * 4, c0 = tx * 8;

    unsigned long long acc[4][4];
#pragma unroll
    for (int i = 0; i < 4; i++)
#pragma unroll
        for (int j = 0; j < 4; j++) acc[i][j] = 0ull;

    for (int kc = 0; kc < K; kc += KC) {
        __syncthreads();
        // X chunk: 128 rows x 32 k, coalesced float4 loads, conflict-free STS
#pragma unroll
        for (int it = 0; it < 4; ++it) {
            int i = tid + it * 256;          // 1024 float4 slots
            int row = i >> 3;
            int k4 = (i & 7) * 4;
            int gr = row0 + row;
            float4 v = make_float4(0.f, 0.f, 0.f, 0.f);
            if (gr < n) v = *(const float4*)&A[(size_t)gr * K + kc + k4];
            Xs[row * XP + k4 + 0] = v.x;
            Xs[row * XP + k4 + 1] = v.y;
            Xs[row * XP + k4 + 2] = v.z;
            Xs[row * XP + k4 + 3] = v.w;
        }
        // W chunk (contiguous)
#pragma unroll
        for (int it = 0; it < 2; ++it) {
            int i = tid + it * 256;
            *(float4*)&Wsh[i * 4] = *(const float4*)&W[(size_t)kc * 64 + i * 4];
        }
        __syncthreads();

#pragma unroll
        for (int k = 0; k < KC; ++k) {
            ulonglong2 wa = *(const ulonglong2*)&Wsh[k * 64 + c0];
            ulonglong2 wb = *(const ulonglong2*)&Wsh[k * 64 + c0 + 4];
#pragma unroll
            for (int i = 0; i < 4; i++) {
                unsigned long long xd = dup2(Xs[(r0 + i) * XP + k]);
                ffma2(acc[i][0], xd, wa.x);
                ffma2(acc[i][1], xd, wa.y);
                ffma2(acc[i][2], xd, wb.x);
                ffma2(acc[i][3], xd, wb.y);
            }
        }
    }

#pragma unroll
    for (int i = 0; i < 4; i++) {
        int gr = row0 + r0 + i;
        if (gr < n) {
            float2 a0 = unpk(acc[i][0]), a1 = unpk(acc[i][1]);
            float2 a2 = unpk(acc[i][2]), a3 = unpk(acc[i][3]);
            *(float4*)&g_t[(size_t)gr * 64 + c0]     = make_float4(a0.x, a0.y, a1.x, a1.y);
            *(float4*)&g_t[(size_t)gr * 64 + c0 + 4] = make_float4(a2.x, a2.y, a3.x, a3.y);
        }
    }
}

// ---------------- propagation: out[d] = sum_{e: dst=d} w_e * g_t[src_e]
//                   + dinv[d]^2 * g_t[d] (+bias) (+relu) ----------------
// out == nullptr -> write g_h. Warp per node, lane owns 2 features,
// register accumulation, CSR meta via shuffle. No atomics.
__global__ __launch_bounds__(256) void k_prop(float* __restrict__ outp,
                                              const float* __restrict__ bias, int relu,
                                              int n) {
    float* out = outp ? outp : g_h;
    int warp = (blockIdx.x * blockDim.x + threadIdx.x) >> 5;
    int lane = threadIdx.x & 31;
    if (warp >= n) return;
    int node = warp;
    int beg = g_off[node], end = g_off[node + 1];
    const float* tf = g_t + 2 * lane;

    float accx = 0.f, accy = 0.f;
    for (int j = beg; j < end; j += 32) {
        int m = end - j;
        if (m > 32) m = 32;
        int s = 0;
        float wv = 0.f;
        if (lane < m) { s = g_src[j + lane]; wv = g_w[j + lane]; }
#pragma unroll 4
        for (int i = 0; i < m; ++i) {
            int si = __shfl_sync(0xffffffffu, s, i);
            float wi = __shfl_sync(0xffffffffu, wv, i);
            float2 v = *(const float2*)(tf + (size_t)si * 64);
            accx = fmaf(wi, v.x, accx);
            accy = fmaf(wi, v.y, accy);
        }
    }
    // self loop
    float dv = g_dinv[node];
    float2 v0 = *(const float2*)(tf + (size_t)node * 64);
    float w0 = dv * dv;
    accx = fmaf(w0, v0.x, accx);
    accy = fmaf(w0, v0.y, accy);
    if (bias) { accx += bias[2 * lane]; accy += bias[2 * lane + 1]; }
    if (relu) { accx = fmaxf(accx, 0.f); accy = fmaxf(accy, 0.f); }
    *(float2*)(out + (size_t)node * 64 + 2 * lane) = make_float2(accx, accy);
}

// ---------------- launch ----------------
extern "C" void kernel_launch(void* const* d_in, const int* in_sizes, int n_in,
                              void* d_out, int out_size) {
    const float* x     = (const float*)d_in[0];
    const int*   ei    = (const int*)d_in[1];     // int32 (JAX x64 disabled)
    const float* W_in  = (const float*)d_in[2];
    const float* b_in  = (const float*)d_in[3];
    const float* W_h   = (const float*)d_in[4];
    const float* b_h   = (const float*)d_in[5];
    const float* W_out = (const float*)d_in[6];

    int n = in_sizes[0] / 128;
    int E = in_sizes[1] / 2;

    int nb1 = (n + 1023) / 1024;

    // CSR build (fresh every call — deterministic)
    k_init   <<<(n + 255) / 256, 256>>>(n);
    k_count  <<<(E + 255) / 256, 256>>>(ei, E);
    k_scan1  <<<nb1, 256>>>(n);                  // fused dinv
    k_scan2  <<<1, 256>>>(nb1);
    k_scanadd<<<(n + 255) / 256, 256>>>(n, E);
    k_scatter<<<(E + 255) / 256, 256>>>(ei, E);

    int gb = (n + 127) / 128;
    int pb = (n + 7) / 8;

    // layer 1: h = prop(x @ W_in) + b_in
    k_gemm<128><<<gb, 256>>>(x, W_in, n);
    k_prop<<<pb, 256>>>(nullptr, b_in, 0, n);

    // hidden layers: h = relu(prop(h @ W_h[l]) + b_h[l])
    for (int l = 0; l < 3; ++l) {
        k_gemm<64><<<gb, 256>>>(nullptr, W_h + (size_t)l * 64 * 64, n);
        k_prop<<<pb, 256>>>(nullptr, b_h + (size_t)l * 64, 1, n);
    }

    // output layer: out = prop(h @ W_out), no bias, no relu
    k_gemm<64><<<gb, 256>>>(nullptr, W_out, n);
    k_prop<<<pb, 256>>>((float*)d_out, nullptr, 0, n);
}

// round 5
// speedup vs baseline: 1.2492x; 1.2492x over previous
#include <cuda_runtime.h>

#define N_MAX 100000
#define E_MAX 1700000

// ---------------- static device scratch (referenced directly in kernels) -----
__device__ __align__(16) float g_t[(size_t)N_MAX * 64];  // GEMM out / prop in
__device__ __align__(16) float g_h[(size_t)N_MAX * 64];  // prop out / GEMM in
__device__ int   g_src[E_MAX];               // CSR: source node per edge (by dst)
__device__ float g_w[E_MAX];                 // CSR: norm weight per edge
__device__ int   g_deg[N_MAX];               // in-degree (incl self loop)
__device__ int   g_cur[N_MAX];               // scatter cursors
__device__ int   g_off[N_MAX + 1];           // CSR offsets, block-LOCAL (add g_bsums)
__device__ float g_dinv[N_MAX];              // deg^-1/2
__device__ int   g_bsums[256];               // scan block sums (exclusive)

__device__ __forceinline__ int foff(int i) {   // final CSR offset
    return g_off[i] + g_bsums[i >> 10];
}

// ---------------- graph preprocessing ----------------
__global__ void k_init(int n) {
    int i = blockIdx.x * blockDim.x + threadIdx.x;
    if (i < n) { g_deg[i] = 1; g_cur[i] = 0; }   // deg starts at 1: self loop
}

// edge_index is int32 (JAX x64 disabled downcasts jnp.int64 -> int32)
__global__ void k_count(const int* __restrict__ ei, int E) {
    int e = blockIdx.x * blockDim.x + threadIdx.x;
    if (e < E) atomicAdd(&g_deg[ei[E + e]], 1);
}

// scan of (deg-1) over 1024-elem tiles, shuffle-based, fused dinv computation
__global__ __launch_bounds__(256) void k_scan1(int n) {
    __shared__ int wsum[8];
    int tid = threadIdx.x;
    int base = blockIdx.x * 1024 + tid * 4;
    int v[4];
#pragma unroll
    for (int j = 0; j < 4; j++) {
        int i = base + j;
        int d = (i < n) ? g_deg[i] : 1;
        v[j] = d - 1;
        if (i < n) g_dinv[i] = rsqrtf((float)d);
    }
    int s = v[0] + v[1] + v[2] + v[3];
    int lane = tid & 31, w = tid >> 5;
    int ps = s;
#pragma unroll
    for (int o = 1; o < 32; o <<= 1) {
        int t = __shfl_up_sync(0xffffffffu, ps, o);
        if (lane >= o) ps += t;
    }
    if (lane == 31) wsum[w] = ps;
    __syncthreads();
    if (w == 0) {
        int t = (lane < 8) ? wsum[lane] : 0;
#pragma unroll
        for (int o = 1; o < 8; o <<= 1) {
            int u = __shfl_up_sync(0xffffffffu, t, o);
            if (lane >= o) t += u;
        }
        if (lane < 8) wsum[lane] = t;
    }
    __syncthreads();
    int run = ps - s + (w ? wsum[w - 1] : 0);   // block-local exclusive
#pragma unroll
    for (int j = 0; j < 4; j++) {
        int i = base + j;
        if (i < n) g_off[i] = run;
        else if (i == n) g_off[n] = run;        // sentinel (block-local)
        run += v[j];
    }
    if (tid == 0) g_bsums[blockIdx.x] = wsum[7];
}

__global__ void k_scan2(int nb) {
    __shared__ int sh[256];
    int tid = threadIdx.x;
    int v = (tid < nb) ? g_bsums[tid] : 0;
    sh[tid] = v;
    __syncthreads();
    for (int o = 1; o < 256; o <<= 1) {
        int t = (tid >= o) ? sh[tid - o] : 0;
        __syncthreads();
        sh[tid] += t;
        __syncthreads();
    }
    if (tid < 256) g_bsums[tid] = sh[tid] - v;   // exclusive (idx >= nb also valid)
}

__global__ void k_scatter(const int* __restrict__ ei, int E) {
    int e = blockIdx.x * blockDim.x + threadIdx.x;
    if (e >= E) return;
    int s = ei[e];
    int d = ei[E + e];
    int pos = foff(d) + atomicAdd(&g_cur[d], 1);
    g_src[pos] = s;
    g_w[pos] = g_dinv[s] * g_dinv[d];
}

// ---------------- packed f32x2 helpers ----------------
__device__ __forceinline__ unsigned long long dup2(float x) {
    unsigned long long r;
    asm("mov.b64 %0, {%1, %1};" : "=l"(r) : "f"(x));
    return r;
}
__device__ __forceinline__ void ffma2(unsigned long long& d,
                                      unsigned long long a, unsigned long long b) {
    asm("fma.rn.f32x2 %0, %1, %2, %0;" : "+l"(d) : "l"(a), "l"(b));
}
__device__ __forceinline__ float2 unpk(unsigned long long v) {
    float2 r;
    asm("mov.b64 {%0, %1}, %2;" : "=f"(r.x), "=f"(r.y) : "l"(v));
    return r;
}

// ---------------- GEMM: g_t[n,64] = A[n,K] @ W[K,64] ----------------
// A == nullptr -> read g_h. R3 tiling (128x64 tile, 256 thr, 8 rows x 4 cols
// per thread) but accumulators pair ADJACENT ROWS: a-operand is a direct
// LDS.64 of (x_r, x_{r+1}) from a pair-interleaved Xs — no per-row dup MOVs.
// Per k: 4 LDS.64 + 1 LDS.128 + 4 W-dups + 16 FFMA2 -> FMA-pipe-bound.
template <int K>
__global__ __launch_bounds__(256) void k_gemm(const float* __restrict__ Ain,
                                              const float* __restrict__ W, int n) {
    const float* A = Ain ? Ain : g_h;
    constexpr int KC = 32;
    constexpr int PF = 2 * KC + 4;                   // 68 floats per pair-row
    __shared__ __align__(16) float Xs[64 * PF];      // [pair][2k + parity]
    __shared__ __align__(16) float Wsh[KC * 64];

    int tid = threadIdx.x;
    int row0 = blockIdx.x * 128;
    int tx = tid & 15, ty = tid >> 4;
    int c0 = tx * 4;
    int p0 = ty * 4;                                 // first row-pair

    unsigned long long acc[4][4];                    // [row-pair][col]
#pragma unroll
    for (int i = 0; i < 4; i++)
#pragma unroll
        for (int j = 0; j < 4; j++) acc[i][j] = 0ull;

    for (int kc = 0; kc < K; kc += KC) {
        __syncthreads();
        // X chunk: coalesced float4 loads, pair-interleaved scalar stores
#pragma unroll
        for (int it = 0; it < 4; ++it) {
            int i = tid + it * 256;          // 1024 float4 slots
            int row = i >> 3;
            int k4 = (i & 7) * 4;
            int gr = row0 + row;
            float4 v = make_float4(0.f, 0.f, 0.f, 0.f);
            if (gr < n) v = *(const float4*)&A[(size_t)gr * K + kc + k4];
            int base = (row >> 1) * PF + (row & 1);
            Xs[base + 2 * (k4 + 0)] = v.x;
            Xs[base + 2 * (k4 + 1)] = v.y;
            Xs[base + 2 * (k4 + 2)] = v.z;
            Xs[base + 2 * (k4 + 3)] = v.w;
        }
        // W chunk (contiguous)
#pragma unroll
        for (int it = 0; it < 2; ++it) {
            int i = tid + it * 256;
            *(float4*)&Wsh[i * 4] = *(const float4*)&W[(size_t)kc * 64 + i * 4];
        }
        __syncthreads();

#pragma unroll
        for (int k = 0; k < KC; ++k) {
            float4 wv = *(const float4*)&Wsh[k * 64 + c0];
            unsigned long long w0 = dup2(wv.x), w1 = dup2(wv.y);
            unsigned long long w2 = dup2(wv.z), w3 = dup2(wv.w);
#pragma unroll
            for (int i = 0; i < 4; i++) {
                unsigned long long x2 =
                    *(const unsigned long long*)&Xs[(p0 + i) * PF + 2 * k];
                ffma2(acc[i][0], x2, w0);
                ffma2(acc[i][1], x2, w1);
                ffma2(acc[i][2], x2, w2);
                ffma2(acc[i][3], x2, w3);
            }
        }
    }

#pragma unroll
    for (int i = 0; i < 4; i++) {
        int gr = row0 + (p0 + i) * 2;
        float2 a0 = unpk(acc[i][0]), a1 = unpk(acc[i][1]);
        float2 a2 = unpk(acc[i][2]), a3 = unpk(acc[i][3]);
        if (gr < n)
            *(float4*)&g_t[(size_t)gr * 64 + c0] = make_float4(a0.x, a1.x, a2.x, a3.x);
        if (gr + 1 < n)
            *(float4*)&g_t[(size_t)(gr + 1) * 64 + c0] = make_float4(a0.y, a1.y, a2.y, a3.y);
    }
}

// ---------------- propagation: out[d] = sum_{e: dst=d} w_e * g_t[src_e]
//                   + dinv[d]^2 * g_t[d] (+bias) (+relu) ----------------
// out == nullptr -> write g_h. Warp per node, lane owns 2 features,
// register accumulation, CSR meta via shuffle. No atomics.
__global__ __launch_bounds__(256) void k_prop(float* __restrict__ outp,
                                              const float* __restrict__ bias, int relu,
                                              int n) {
    float* out = outp ? outp : g_h;
    int warp = (blockIdx.x * blockDim.x + threadIdx.x) >> 5;
    int lane = threadIdx.x & 31;
    if (warp >= n) return;
    int node = warp;
    int beg = foff(node), end = foff(node + 1);
    const float* tf = g_t + 2 * lane;

    float accx = 0.f, accy = 0.f;
    for (int j = beg; j < end; j += 32) {
        int m = end - j;
        if (m > 32) m = 32;
        int s = 0;
        float wv = 0.f;
        if (lane < m) { s = g_src[j + lane]; wv = g_w[j + lane]; }
#pragma unroll 4
        for (int i = 0; i < m; ++i) {
            int si = __shfl_sync(0xffffffffu, s, i);
            float wi = __shfl_sync(0xffffffffu, wv, i);
            float2 v = *(const float2*)(tf + (size_t)si * 64);
            accx = fmaf(wi, v.x, accx);
            accy = fmaf(wi, v.y, accy);
        }
    }
    // self loop
    float dv = g_dinv[node];
    float2 v0 = *(const float2*)(tf + (size_t)node * 64);
    float w0 = dv * dv;
    accx = fmaf(w0, v0.x, accx);
    accy = fmaf(w0, v0.y, accy);
    if (bias) { accx += bias[2 * lane]; accy += bias[2 * lane + 1]; }
    if (relu) { accx = fmaxf(accx, 0.f); accy = fmaxf(accy, 0.f); }
    *(float2*)(out + (size_t)node * 64 + 2 * lane) = make_float2(accx, accy);
}

// ---------------- launch ----------------
extern "C" void kernel_launch(void* const* d_in, const int* in_sizes, int n_in,
                              void* d_out, int out_size) {
    const float* x     = (const float*)d_in[0];
    const int*   ei    = (const int*)d_in[1];     // int32 (JAX x64 disabled)
    const float* W_in  = (const float*)d_in[2];
    const float* b_in  = (const float*)d_in[3];
    const float* W_h   = (const float*)d_in[4];
    const float* b_h   = (const float*)d_in[5];
    const float* W_out = (const float*)d_in[6];

    int n = in_sizes[0] / 128;
    int E = in_sizes[1] / 2;

    int nb1 = (n + 1023) / 1024;

    // CSR build (fresh every call — deterministic). 5 launches; the 6th
    // launch (profile slot 5) is the big K=128 GEMM.
    k_init   <<<(n + 255) / 256, 256>>>(n);
    k_count  <<<(E + 255) / 256, 256>>>(ei, E);
    k_scan1  <<<nb1, 256>>>(n);                  // fused dinv + sentinel
    k_scan2  <<<1, 256>>>(nb1);
    k_scatter<<<(E + 255) / 256, 256>>>(ei, E);

    int gb = (n + 127) / 128;
    int pb = (n + 7) / 8;

    // layer 1: h = prop(x @ W_in) + b_in
    k_gemm<128><<<gb, 256>>>(x, W_in, n);
    k_prop<<<pb, 256>>>(nullptr, b_in, 0, n);

    // hidden layers: h = relu(prop(h @ W_h[l]) + b_h[l])
    for (int l = 0; l < 3; ++l) {
        k_gemm<64><<<gb, 256>>>(nullptr, W_h + (size_t)l * 64 * 64, n);
        k_prop<<<pb, 256>>>(nullptr, b_h + (size_t)l * 64, 1, n);
    }

    // output layer: out = prop(h @ W_out), no bias, no relu
    k_gemm<64><<<gb, 256>>>(nullptr, W_out, n);
    k_prop<<<pb, 256>>>((float*)d_out, nullptr, 0, n);
}

// round 6
// speedup vs baseline: 1.3443x; 1.0762x over previous
#include <cuda_runtime.h>

#define N_MAX 100000
#define E_MAX 1700000

// ---------------- static device scratch (referenced directly in kernels) -----
__device__ __align__(16) float g_t[(size_t)N_MAX * 64];  // GEMM out / prop in
__device__ __align__(16) float g_h[(size_t)N_MAX * 64];  // prop out / GEMM in
__device__ __align__(16) int2  g_meta[E_MAX];  // CSR: (src, w-bits) per edge (by dst)
__device__ int   g_deg[N_MAX];               // in-degree (incl self loop)
__device__ int   g_cur[N_MAX];               // scatter cursors
__device__ int   g_off[N_MAX + 1];           // CSR offsets, block-LOCAL (add g_bsums)
__device__ float g_dinv[N_MAX];              // deg^-1/2
__device__ int   g_bsums[256];               // scan block sums (exclusive)

__device__ __forceinline__ int foff(int i) {   // final CSR offset
    return g_off[i] + g_bsums[i >> 10];
}

// ---------------- side stream for fork-join overlap (created pre-baseline) ---
static cudaStream_t g_s2;
static cudaEvent_t  g_evA, g_evB;
static struct SideInit {
    SideInit() {
        cudaStreamCreateWithFlags(&g_s2, cudaStreamNonBlocking);
        cudaEventCreateWithFlags(&g_evA, cudaEventDisableTiming);
        cudaEventCreateWithFlags(&g_evB, cudaEventDisableTiming);
    }
} g_side_init;

// ---------------- graph preprocessing ----------------
__global__ void k_init(int n) {
    int i = blockIdx.x * blockDim.x + threadIdx.x;
    if (i < n) { g_deg[i] = 1; g_cur[i] = 0; }   // deg starts at 1: self loop
}

// edge_index is int32 (JAX x64 disabled downcasts jnp.int64 -> int32)
__global__ void k_count(const int* __restrict__ ei, int E) {
    int e = blockIdx.x * blockDim.x + threadIdx.x;
    if (e < E) atomicAdd(&g_deg[ei[E + e]], 1);
}

// scan of (deg-1) over 1024-elem tiles, shuffle-based, fused dinv computation
__global__ __launch_bounds__(256) void k_scan1(int n) {
    __shared__ int wsum[8];
    int tid = threadIdx.x;
    int base = blockIdx.x * 1024 + tid * 4;
    int v[4];
#pragma unroll
    for (int j = 0; j < 4; j++) {
        int i = base + j;
        int d = (i < n) ? g_deg[i] : 1;
        v[j] = d - 1;
        if (i < n) g_dinv[i] = rsqrtf((float)d);
    }
    int s = v[0] + v[1] + v[2] + v[3];
    int lane = tid & 31, w = tid >> 5;
    int ps = s;
#pragma unroll
    for (int o = 1; o < 32; o <<= 1) {
        int t = __shfl_up_sync(0xffffffffu, ps, o);
        if (lane >= o) ps += t;
    }
    if (lane == 31) wsum[w] = ps;
    __syncthreads();
    if (w == 0) {
        int t = (lane < 8) ? wsum[lane] : 0;
#pragma unroll
        for (int o = 1; o < 8; o <<= 1) {
            int u = __shfl_up_sync(0xffffffffu, t, o);
            if (lane >= o) t += u;
        }
        if (lane < 8) wsum[lane] = t;
    }
    __syncthreads();
    int run = ps - s + (w ? wsum[w - 1] : 0);   // block-local exclusive
#pragma unroll
    for (int j = 0; j < 4; j++) {
        int i = base + j;
        if (i < n) g_off[i] = run;
        else if (i == n) g_off[n] = run;        // sentinel (block-local)
        run += v[j];
    }
    if (tid == 0) g_bsums[blockIdx.x] = wsum[7];
}

__global__ void k_scan2(int nb) {
    __shared__ int sh[256];
    int tid = threadIdx.x;
    int v = (tid < nb) ? g_bsums[tid] : 0;
    sh[tid] = v;
    __syncthreads();
    for (int o = 1; o < 256; o <<= 1) {
        int t = (tid >= o) ? sh[tid - o] : 0;
        __syncthreads();
        sh[tid] += t;
        __syncthreads();
    }
    if (tid < 256) g_bsums[tid] = sh[tid] - v;   // exclusive (idx >= nb also valid)
}

__global__ void k_scatter(const int* __restrict__ ei, int E) {
    int e = blockIdx.x * blockDim.x + threadIdx.x;
    if (e >= E) return;
    int s = ei[e];
    int d = ei[E + e];
    int pos = foff(d) + atomicAdd(&g_cur[d], 1);
    g_meta[pos] = make_int2(s, __float_as_int(g_dinv[s] * g_dinv[d]));
}

// ---------------- packed f32x2 helpers ----------------
__device__ __forceinline__ unsigned long long dup2(float x) {
    unsigned long long r;
    asm("mov.b64 %0, {%1, %1};" : "=l"(r) : "f"(x));
    return r;
}
__device__ __forceinline__ void ffma2(unsigned long long& d,
                                      unsigned long long a, unsigned long long b) {
    asm("fma.rn.f32x2 %0, %1, %2, %0;" : "+l"(d) : "l"(a), "l"(b));
}
__device__ __forceinline__ float2 unpk(unsigned long long v) {
    float2 r;
    asm("mov.b64 {%0, %1}, %2;" : "=f"(r.x), "=f"(r.y) : "l"(v));
    return r;
}

// ---------------- GEMM: g_t[n,64] = A[n,K] @ W[K,64] ----------------
// A == nullptr -> read g_h. 128x64 tile, 256 thr; accumulators pair ADJACENT
// ROWS: a-operand is a direct LDS.64 of (x_r, x_{r+1}) from pair-interleaved Xs.
// Per k: 4 LDS.64 + 1 LDS.128 + 4 W-dups + 16 FFMA2 -> FMA-pipe-bound.
template <int K>
__global__ __launch_bounds__(256) void k_gemm(const float* __restrict__ Ain,
                                              const float* __restrict__ W, int n) {
    const float* A = Ain ? Ain : g_h;
    constexpr int KC = 32;
    constexpr int PF = 2 * KC + 4;                   // 68 floats per pair-row
    __shared__ __align__(16) float Xs[64 * PF];      // [pair][2k + parity]
    __shared__ __align__(16) float Wsh[KC * 64];

    int tid = threadIdx.x;
    int row0 = blockIdx.x * 128;
    int tx = tid & 15, ty = tid >> 4;
    int c0 = tx * 4;
    int p0 = ty * 4;                                 // first row-pair

    unsigned long long acc[4][4];                    // [row-pair][col]
#pragma unroll
    for (int i = 0; i < 4; i++)
#pragma unroll
        for (int j = 0; j < 4; j++) acc[i][j] = 0ull;

    for (int kc = 0; kc < K; kc += KC) {
        __syncthreads();
        // X chunk: coalesced float4 loads, pair-interleaved scalar stores
#pragma unroll
        for (int it = 0; it < 4; ++it) {
            int i = tid + it * 256;          // 1024 float4 slots
            int row = i >> 3;
            int k4 = (i & 7) * 4;
            int gr = row0 + row;
            float4 v = make_float4(0.f, 0.f, 0.f, 0.f);
            if (gr < n) v = *(const float4*)&A[(size_t)gr * K + kc + k4];
            int base = (row >> 1) * PF + (row & 1);
            Xs[base + 2 * (k4 + 0)] = v.x;
            Xs[base + 2 * (k4 + 1)] = v.y;
            Xs[base + 2 * (k4 + 2)] = v.z;
            Xs[base + 2 * (k4 + 3)] = v.w;
        }
        // W chunk (contiguous)
#pragma unroll
        for (int it = 0; it < 2; ++it) {
            int i = tid + it * 256;
            *(float4*)&Wsh[i * 4] = *(const float4*)&W[(size_t)kc * 64 + i * 4];
        }
        __syncthreads();

#pragma unroll
        for (int k = 0; k < KC; ++k) {
            float4 wv = *(const float4*)&Wsh[k * 64 + c0];
            unsigned long long w0 = dup2(wv.x), w1 = dup2(wv.y);
            unsigned long long w2 = dup2(wv.z), w3 = dup2(wv.w);
#pragma unroll
            for (int i = 0; i < 4; i++) {
                unsigned long long x2 =
                    *(const unsigned long long*)&Xs[(p0 + i) * PF + 2 * k];
                ffma2(acc[i][0], x2, w0);
                ffma2(acc[i][1], x2, w1);
                ffma2(acc[i][2], x2, w2);
                ffma2(acc[i][3], x2, w3);
            }
        }
    }

#pragma unroll
    for (int i = 0; i < 4; i++) {
        int gr = row0 + (p0 + i) * 2;
        float2 a0 = unpk(acc[i][0]), a1 = unpk(acc[i][1]);
        float2 a2 = unpk(acc[i][2]), a3 = unpk(acc[i][3]);
        if (gr < n)
            *(float4*)&g_t[(size_t)gr * 64 + c0] = make_float4(a0.x, a1.x, a2.x, a3.x);
        if (gr + 1 < n)
            *(float4*)&g_t[(size_t)(gr + 1) * 64 + c0] = make_float4(a0.y, a1.y, a2.y, a3.y);
    }
}

// ---------------- propagation: out[d] = sum_{e: dst=d} w_e * g_t[src_e]
//                   + dinv[d]^2 * g_t[d] (+bias) (+relu) ----------------
// out == nullptr -> write g_h. Warp per node, lane owns 2 features,
// register accumulation, packed CSR meta via one LDG.64 + shuffle. No atomics.
__global__ __launch_bounds__(256) void k_prop(float* __restrict__ outp,
                                              const float* __restrict__ bias, int relu,
                                              int n) {
    float* out = outp ? outp : g_h;
    int warp = (blockIdx.x * blockDim.x + threadIdx.x) >> 5;
    int lane = threadIdx.x & 31;
    if (warp >= n) return;
    int node = warp;
    int beg = foff(node), end = foff(node + 1);
    const float* tf = g_t + 2 * lane;

    float accx = 0.f, accy = 0.f;
    for (int j = beg; j < end; j += 32) {
        int m = end - j;
        if (m > 32) m = 32;
        int s = 0;
        float wv = 0.f;
        if (lane < m) {
            int2 mw = g_meta[j + lane];
            s = mw.x;
            wv = __int_as_float(mw.y);
        }
#pragma unroll 4
        for (int i = 0; i < m; ++i) {
            int si = __shfl_sync(0xffffffffu, s, i);
            float wi = __shfl_sync(0xffffffffu, wv, i);
            float2 v = *(const float2*)(tf + (size_t)si * 64);
            accx = fmaf(wi, v.x, accx);
            accy = fmaf(wi, v.y, accy);
        }
    }
    // self loop
    float dv = g_dinv[node];
    float2 v0 = *(const float2*)(tf + (size_t)node * 64);
    float w0 = dv * dv;
    accx = fmaf(w0, v0.x, accx);
    accy = fmaf(w0, v0.y, accy);
    if (bias) { accx += bias[2 * lane]; accy += bias[2 * lane + 1]; }
    if (relu) { accx = fmaxf(accx, 0.f); accy = fmaxf(accy, 0.f); }
    *(float2*)(out + (size_t)node * 64 + 2 * lane) = make_float2(accx, accy);
}

// ---------------- launch ----------------
extern "C" void kernel_launch(void* const* d_in, const int* in_sizes, int n_in,
                              void* d_out, int out_size) {
    const float* x     = (const float*)d_in[0];
    const int*   ei    = (const int*)d_in[1];     // int32 (JAX x64 disabled)
    const float* W_in  = (const float*)d_in[2];
    const float* b_in  = (const float*)d_in[3];
    const float* W_h   = (const float*)d_in[4];
    const float* b_h   = (const float*)d_in[5];
    const float* W_out = (const float*)d_in[6];

    int n = in_sizes[0] / 128;
    int E = in_sizes[1] / 2;

    int nb1 = (n + 1023) / 1024;
    int gb = (n + 127) / 128;
    int pb = (n + 7) / 8;

    // Fork: CSR build on side stream, concurrently with the first GEMM on
    // the main stream. Both are event-linked (graph-capturable fork/join).
    cudaEventRecord(g_evA, 0);
    cudaStreamWaitEvent(g_s2, g_evA, 0);

    k_init   <<<(n + 255) / 256, 256, 0, g_s2>>>(n);
    k_count  <<<(E + 255) / 256, 256, 0, g_s2>>>(ei, E);
    k_scan1  <<<nb1, 256, 0, g_s2>>>(n);         // fused dinv + sentinel
    k_scan2  <<<1, 256, 0, g_s2>>>(nb1);
    k_scatter<<<(E + 255) / 256, 256, 0, g_s2>>>(ei, E);
    cudaEventRecord(g_evB, g_s2);

    // layer 1 GEMM overlaps the CSR build
    k_gemm<128><<<gb, 256>>>(x, W_in, n);

    // Join: prop needs both GEMM output and CSR
    cudaStreamWaitEvent(0, g_evB, 0);
    k_prop<<<pb, 256>>>(nullptr, b_in, 0, n);

    // hidden layers: h = relu(prop(h @ W_h[l]) + b_h[l])
    for (int l = 0; l < 3; ++l) {
        k_gemm<64><<<gb, 256>>>(nullptr, W_h + (size_t)l * 64 * 64, n);
        k_prop<<<pb, 256>>>(nullptr, b_h + (size_t)l * 64, 1, n);
    }

    // output layer: out = prop(h @ W_out), no bias, no relu
    k_gemm<64><<<gb, 256>>>(nullptr, W_out, n);
    k_prop<<<pb, 256>>>((float*)d_out, nullptr, 0, n);
}